// round 1
// baseline (speedup 1.0000x reference)
#include <cuda_runtime.h>
#include <math.h>

#define D 128
#define H 4
#define DK 32
#define BATCH 16
#define SEQ 2048
#define ROWS (BATCH*SEQ)   // 32768
#define LNEPS 1e-5f

// ---------------- scratch (static device globals; no allocs allowed) ----------
__device__ float g_xn[ROWS*D];
__device__ float g_q [ROWS*D];
__device__ float g_k [ROWS*D];
__device__ float g_v [ROWS*D];
__device__ float g_attn[ROWS*D];
__device__ float g_sa[ROWS*D];
__device__ float g_h [ROWS*D];
__device__ float g_f1[ROWS*D];

// ---------------- LayerNorm (optionally fused residual add) -------------------
// 1 warp per row of 128; 8 rows per 256-thread block.
__global__ void ln_kernel(const float* __restrict__ in, const float* __restrict__ add,
                          float* __restrict__ sum_out, float* __restrict__ ln_out,
                          const float* __restrict__ w, const float* __restrict__ b) {
    int row  = blockIdx.x * 8 + (threadIdx.x >> 5);
    int lane = threadIdx.x & 31;
    const float4* ip = (const float4*)(in + row * D);
    float4 v = ip[lane];
    if (add != nullptr) {
        float4 a = ((const float4*)(add + row * D))[lane];
        v.x += a.x; v.y += a.y; v.z += a.z; v.w += a.w;
        ((float4*)(sum_out + row * D))[lane] = v;
    }
    float s = v.x + v.y + v.z + v.w;
    #pragma unroll
    for (int o = 16; o; o >>= 1) s += __shfl_xor_sync(0xffffffffu, s, o);
    float mu = s * (1.0f / D);
    float dx = v.x - mu, dy = v.y - mu, dz = v.z - mu, dw = v.w - mu;
    float ss = dx*dx + dy*dy + dz*dz + dw*dw;
    #pragma unroll
    for (int o = 16; o; o >>= 1) ss += __shfl_xor_sync(0xffffffffu, ss, o);
    float rstd = rsqrtf(ss * (1.0f / D) + LNEPS);
    float4 wv = ((const float4*)w)[lane];
    float4 bv = ((const float4*)b)[lane];
    float4 o4;
    o4.x = dx * rstd * wv.x + bv.x;
    o4.y = dy * rstd * wv.y + bv.y;
    o4.z = dz * rstd * wv.z + bv.z;
    o4.w = dw * rstd * wv.w + bv.w;
    ((float4*)(ln_out + row * D))[lane] = o4;
}

// ---------------- tiled GEMM helpers ------------------------------------------
// C[M,128] = A[M,128] @ W[128,128]^T (+bias)(relu)(+res)
// 64x64 tiles, K=128 whole. smem stored k-major with pad of 4 to keep float4
// alignment AND avoid bank conflicts.
#define GP 68               // 64 + 4 pad
#define GEMM_SMEM (2*128*GP*4)

__device__ __forceinline__ void load_tileA(float* sA, const float* __restrict__ A,
                                           int rowBase, int tid) {
    for (int idx = tid; idx < 64 * 128; idx += 256) {
        int r = idx >> 7, kk = idx & 127;
        sA[kk * GP + r] = A[(rowBase + r) * D + kk];
    }
}
__device__ __forceinline__ void load_tileW(float* sW, const float* __restrict__ W,
                                           int colBase, int tid) {
    for (int idx = tid; idx < 64 * 128; idx += 256) {
        int c = idx >> 7, kk = idx & 127;
        sW[kk * GP + c] = W[(colBase + c) * D + kk];
    }
}

__device__ __forceinline__ void mm_64x64(const float* sA, const float* sW,
                                         int ty, int tx, float acc[4][4]) {
    #pragma unroll 4
    for (int kk = 0; kk < 128; kk++) {
        float4 a4 = *(const float4*)&sA[kk * GP + ty * 4];
        float4 w4 = *(const float4*)&sW[kk * GP + tx * 4];
        float av[4] = {a4.x, a4.y, a4.z, a4.w};
        float wv[4] = {w4.x, w4.y, w4.z, w4.w};
        #pragma unroll
        for (int i = 0; i < 4; i++)
            #pragma unroll
            for (int j = 0; j < 4; j++)
                acc[i][j] += av[i] * wv[j];
    }
}

// fused QKV: reuse A tile for wq/wk/wv; relu on Q
__global__ __launch_bounds__(256) void qkv_kernel(const float* __restrict__ A,
        const float* __restrict__ wq, const float* __restrict__ wk,
        const float* __restrict__ wv,
        float* __restrict__ q, float* __restrict__ k, float* __restrict__ v) {
    extern __shared__ float smem[];
    float* sA = smem;
    float* sW = smem + 128 * GP;
    int tid = threadIdx.x;
    int rowBase = blockIdx.x * 64;
    int colBase = blockIdx.y * 64;
    int tx = tid & 15, ty = tid >> 4;

    load_tileA(sA, A, rowBase, tid);

    const float* Ws[3] = {wq, wk, wv};
    float*       Os[3] = {q, k, v};
    for (int widx = 0; widx < 3; widx++) {
        __syncthreads();                      // prev compute done / sA ready
        load_tileW(sW, Ws[widx], colBase, tid);
        __syncthreads();
        float acc[4][4] = {};
        mm_64x64(sA, sW, ty, tx, acc);
        float* O = Os[widx];
        bool relu = (widx == 0);
        #pragma unroll
        for (int i = 0; i < 4; i++) {
            float4 o4;
            o4.x = acc[i][0]; o4.y = acc[i][1]; o4.z = acc[i][2]; o4.w = acc[i][3];
            if (relu) {
                o4.x = fmaxf(o4.x, 0.f); o4.y = fmaxf(o4.y, 0.f);
                o4.z = fmaxf(o4.z, 0.f); o4.w = fmaxf(o4.w, 0.f);
            }
            *(float4*)&O[(rowBase + ty * 4 + i) * D + colBase + tx * 4] = o4;
        }
    }
}

template<bool RELU, bool RES>
__global__ __launch_bounds__(256) void gemm_kernel(const float* __restrict__ A,
        const float* __restrict__ W, const float* __restrict__ bias,
        const float* __restrict__ res, float* __restrict__ C) {
    extern __shared__ float smem[];
    float* sA = smem;
    float* sW = smem + 128 * GP;
    int tid = threadIdx.x;
    int rowBase = blockIdx.x * 64;
    int colBase = blockIdx.y * 64;
    int tx = tid & 15, ty = tid >> 4;

    load_tileA(sA, A, rowBase, tid);
    load_tileW(sW, W, colBase, tid);
    __syncthreads();
    float acc[4][4] = {};
    mm_64x64(sA, sW, ty, tx, acc);

    float4 b4 = *(const float4*)&bias[colBase + tx * 4];
    #pragma unroll
    for (int i = 0; i < 4; i++) {
        int row = rowBase + ty * 4 + i;
        float4 o4;
        o4.x = acc[i][0] + b4.x; o4.y = acc[i][1] + b4.y;
        o4.z = acc[i][2] + b4.z; o4.w = acc[i][3] + b4.w;
        if (RELU) {
            o4.x = fmaxf(o4.x, 0.f); o4.y = fmaxf(o4.y, 0.f);
            o4.z = fmaxf(o4.z, 0.f); o4.w = fmaxf(o4.w, 0.f);
        }
        if (RES) {
            float4 r4 = *(const float4*)&res[row * D + colBase + tx * 4];
            o4.x += r4.x; o4.y += r4.y; o4.z += r4.z; o4.w += r4.w;
        }
        *(float4*)&C[row * D + colBase + tx * 4] = o4;
    }
}

// ---------------- flash attention ----------------------------------------------
// grid: (SEQ/256, B*H). 256 threads, 1 query per thread. K/V tiles of 128 keys
// in smem (all-lane broadcast reads). Online softmax, chunked lazy rescale,
// uniform mask-skip (mask identical across the warp for a given key).
#define KT 128
__global__ __launch_bounds__(256) void attn_kernel(const float* __restrict__ gq,
        const float* __restrict__ gk, const float* __restrict__ gv,
        const int* __restrict__ mask, float* __restrict__ out) {
    __shared__ float sK[KT][DK];
    __shared__ float sV[KT][DK];
    __shared__ int   sM[KT];
    int tid = threadIdx.x;
    int b = blockIdx.y >> 2;       // / H
    int h = blockIdx.y & 3;        // % H
    int qi = blockIdx.x * 256 + tid;

    const float* qrow = gq + (b * SEQ + qi) * D + h * DK;
    float qv[DK];
    #pragma unroll
    for (int d = 0; d < DK; d += 4) {
        float4 t = *(const float4*)(qrow + d);
        qv[d] = t.x; qv[d+1] = t.y; qv[d+2] = t.z; qv[d+3] = t.w;
    }
    float m = -1e4f, l = 0.f;
    float acc[DK] = {};
    const float scale = 0.17677669529663687f;   // 1/sqrt(32)

    for (int kb = 0; kb < SEQ; kb += KT) {
        __syncthreads();
        int base = (b * SEQ + kb) * D + h * DK;
        for (int i = tid; i < KT * 8; i += 256) {
            int key = i >> 3, d4 = (i & 7) * 4;
            *(float4*)&sK[key][d4] = *(const float4*)&gk[base + key * D + d4];
            *(float4*)&sV[key][d4] = *(const float4*)&gv[base + key * D + d4];
        }
        if (tid < KT) sM[tid] = mask[b * SEQ + kb + tid];
        __syncthreads();

        for (int c = 0; c < KT; c += 16) {
            float sarr[16];
            float cmax = -1e30f;
            #pragma unroll
            for (int jj = 0; jj < 16; jj++) {
                int j = c + jj;
                if (sM[j]) {                      // uniform across warp
                    float s = 0.f;
                    #pragma unroll
                    for (int d = 0; d < DK; d++) s += qv[d] * sK[j][d];
                    s *= scale;
                    sarr[jj] = s;
                    cmax = fmaxf(cmax, s);
                } else {
                    sarr[jj] = -1e30f;
                }
            }
            if (cmax > m) {                        // lazy rescale (amortized)
                float corr = __expf(m - cmax);
                l *= corr;
                #pragma unroll
                for (int d = 0; d < DK; d++) acc[d] *= corr;
                m = cmax;
            }
            #pragma unroll
            for (int jj = 0; jj < 16; jj++) {
                int j = c + jj;
                if (!sM[j]) continue;              // uniform across warp
                float p = __expf(sarr[jj] - m);
                l += p;
                #pragma unroll
                for (int d = 0; d < DK; d++) acc[d] += p * sV[j][d];
            }
        }
    }
    float inv = 1.f / l;
    float* orow = out + (b * SEQ + qi) * D + h * DK;
    #pragma unroll
    for (int d = 0; d < DK; d += 4) {
        float4 o4;
        o4.x = acc[d] * inv; o4.y = acc[d+1] * inv;
        o4.z = acc[d+2] * inv; o4.w = acc[d+3] * inv;
        *(float4*)(orow + d) = o4;
    }
}

// ---------------- launch ---------------------------------------------------------
extern "C" void kernel_launch(void* const* d_in, const int* in_sizes, int n_in,
                              void* d_out, int out_size) {
    const float* x    = (const float*)d_in[0];
    const int*   mask = (const int*)  d_in[1];
    const float* ln_w = (const float*)d_in[2];
    const float* ln_b = (const float*)d_in[3];
    const float* wq   = (const float*)d_in[4];
    const float* wk   = (const float*)d_in[5];
    const float* wv   = (const float*)d_in[6];
    const float* w1   = (const float*)d_in[7];
    const float* b1   = (const float*)d_in[8];
    const float* w2   = (const float*)d_in[9];
    const float* b2   = (const float*)d_in[10];
    float* out = (float*)d_out;

    float *xn, *q, *k, *v, *attn, *sa, *h, *f1;
    cudaGetSymbolAddress((void**)&xn,   g_xn);
    cudaGetSymbolAddress((void**)&q,    g_q);
    cudaGetSymbolAddress((void**)&k,    g_k);
    cudaGetSymbolAddress((void**)&v,    g_v);
    cudaGetSymbolAddress((void**)&attn, g_attn);
    cudaGetSymbolAddress((void**)&sa,   g_sa);
    cudaGetSymbolAddress((void**)&h,    g_h);
    cudaGetSymbolAddress((void**)&f1,   g_f1);

    cudaFuncSetAttribute(qkv_kernel, cudaFuncAttributeMaxDynamicSharedMemorySize, GEMM_SMEM);
    cudaFuncSetAttribute(gemm_kernel<true,false>,  cudaFuncAttributeMaxDynamicSharedMemorySize, GEMM_SMEM);
    cudaFuncSetAttribute(gemm_kernel<false,true>,  cudaFuncAttributeMaxDynamicSharedMemorySize, GEMM_SMEM);

    // 1) xn = LN(x)
    ln_kernel<<<ROWS/8, 256>>>(x, nullptr, nullptr, xn, ln_w, ln_b);
    // 2) q=relu(xn@wq^T), k, v
    qkv_kernel<<<dim3(ROWS/64, 2), 256, GEMM_SMEM>>>(xn, wq, wk, wv, q, k, v);
    // 3) attention
    attn_kernel<<<dim3(SEQ/256, BATCH*H), 256>>>(q, k, v, mask, attn);
    // 4) sa = xn + attn ; h = LN(sa)
    ln_kernel<<<ROWS/8, 256>>>(attn, xn, sa, h, ln_w, ln_b);
    // 5) f1 = relu(h@w1^T + b1)
    gemm_kernel<true,false><<<dim3(ROWS/64, 2), 256, GEMM_SMEM>>>(h, w1, b1, nullptr, f1);
    // 6) out = sa + f1@w2^T + b2
    gemm_kernel<false,true><<<dim3(ROWS/64, 2), 256, GEMM_SMEM>>>(f1, w2, b2, sa, out);
}

// round 2
// speedup vs baseline: 2.0686x; 2.0686x over previous
#include <cuda_runtime.h>
#include <math.h>

#define D 128
#define H 4
#define DK 32
#define BATCH 16
#define SEQ 2048
#define ROWS (BATCH*SEQ)   // 32768
#define LNEPS 1e-5f

// ---------------- scratch (static device globals; no allocs allowed) ----------
__device__ float g_xn[ROWS*D];
__device__ float g_q [ROWS*D];
__device__ float g_k [ROWS*D];
__device__ float g_v [ROWS*D];
__device__ float g_attn[ROWS*D];
__device__ float g_sa[ROWS*D];
__device__ float g_h [ROWS*D];
__device__ float g_f1[ROWS*D];
__device__ int   g_cnt[BATCH];
__device__ int   g_idx[BATCH*SEQ];

// ---------------- LayerNorm (optionally fused residual add) -------------------
__global__ void ln_kernel(const float* __restrict__ in, const float* __restrict__ add,
                          float* __restrict__ sum_out, float* __restrict__ ln_out,
                          const float* __restrict__ w, const float* __restrict__ b) {
    int row  = blockIdx.x * 8 + (threadIdx.x >> 5);
    int lane = threadIdx.x & 31;
    const float4* ip = (const float4*)(in + row * D);
    float4 v = ip[lane];
    if (add != nullptr) {
        float4 a = ((const float4*)(add + row * D))[lane];
        v.x += a.x; v.y += a.y; v.z += a.z; v.w += a.w;
        ((float4*)(sum_out + row * D))[lane] = v;
    }
    float s = v.x + v.y + v.z + v.w;
    #pragma unroll
    for (int o = 16; o; o >>= 1) s += __shfl_xor_sync(0xffffffffu, s, o);
    float mu = s * (1.0f / D);
    float dx = v.x - mu, dy = v.y - mu, dz = v.z - mu, dw = v.w - mu;
    float ss = dx*dx + dy*dy + dz*dz + dw*dw;
    #pragma unroll
    for (int o = 16; o; o >>= 1) ss += __shfl_xor_sync(0xffffffffu, ss, o);
    float rstd = rsqrtf(ss * (1.0f / D) + LNEPS);
    float4 wv = ((const float4*)w)[lane];
    float4 bv = ((const float4*)b)[lane];
    float4 o4;
    o4.x = dx * rstd * wv.x + bv.x;
    o4.y = dy * rstd * wv.y + bv.y;
    o4.z = dz * rstd * wv.z + bv.z;
    o4.w = dw * rstd * wv.w + bv.w;
    ((float4*)(ln_out + row * D))[lane] = o4;
}

// ---------------- mask compaction (deterministic, order-preserving) -----------
__global__ void compact_kernel(const int* __restrict__ mask,
                               int* __restrict__ idx, int* __restrict__ cnt) {
    int b = blockIdx.x, t = threadIdx.x;
    const int* mb = mask + b * SEQ;
    int m0 = mb[2*t], m1 = mb[2*t+1];
    int s = m0 + m1;
    int lane = t & 31, w = t >> 5;
    int v = s;
    #pragma unroll
    for (int o = 1; o < 32; o <<= 1) {
        int u = __shfl_up_sync(0xffffffffu, v, o);
        if (lane >= o) v += u;
    }
    __shared__ int wsum[32];
    if (lane == 31) wsum[w] = v;
    __syncthreads();
    if (t < 32) {
        int u = wsum[t];
        #pragma unroll
        for (int o = 1; o < 32; o <<= 1) {
            int x = __shfl_up_sync(0xffffffffu, u, o);
            if (t >= o) u += x;
        }
        wsum[t] = u;
    }
    __syncthreads();
    int p = v - s + (w ? wsum[w-1] : 0);
    if (m0) idx[b*SEQ + p++] = 2*t;
    if (m1) idx[b*SEQ + p]   = 2*t + 1;
    if (t == 1023) cnt[b] = wsum[31];
}

// ---------------- tiled GEMM (fp32, unchanged) ---------------------------------
#define GP 68
#define GEMM_SMEM (2*128*GP*4)

__device__ __forceinline__ void load_tileA(float* sA, const float* __restrict__ A,
                                           int rowBase, int tid) {
    for (int idx = tid; idx < 64 * 128; idx += 256) {
        int r = idx >> 7, kk = idx & 127;
        sA[kk * GP + r] = A[(rowBase + r) * D + kk];
    }
}
__device__ __forceinline__ void load_tileW(float* sW, const float* __restrict__ W,
                                           int colBase, int tid) {
    for (int idx = tid; idx < 64 * 128; idx += 256) {
        int c = idx >> 7, kk = idx & 127;
        sW[kk * GP + c] = W[(colBase + c) * D + kk];
    }
}
__device__ __forceinline__ void mm_64x64(const float* sA, const float* sW,
                                         int ty, int tx, float acc[4][4]) {
    #pragma unroll 4
    for (int kk = 0; kk < 128; kk++) {
        float4 a4 = *(const float4*)&sA[kk * GP + ty * 4];
        float4 w4 = *(const float4*)&sW[kk * GP + tx * 4];
        float av[4] = {a4.x, a4.y, a4.z, a4.w};
        float wv[4] = {w4.x, w4.y, w4.z, w4.w};
        #pragma unroll
        for (int i = 0; i < 4; i++)
            #pragma unroll
            for (int j = 0; j < 4; j++)
                acc[i][j] += av[i] * wv[j];
    }
}

__global__ __launch_bounds__(256) void qkv_kernel(const float* __restrict__ A,
        const float* __restrict__ wq, const float* __restrict__ wk,
        const float* __restrict__ wv,
        float* __restrict__ q, float* __restrict__ k, float* __restrict__ v) {
    extern __shared__ float smem[];
    float* sA = smem;
    float* sW = smem + 128 * GP;
    int tid = threadIdx.x;
    int rowBase = blockIdx.x * 64;
    int colBase = blockIdx.y * 64;
    int tx = tid & 15, ty = tid >> 4;

    load_tileA(sA, A, rowBase, tid);

    const float* Ws[3] = {wq, wk, wv};
    float*       Os[3] = {q, k, v};
    for (int widx = 0; widx < 3; widx++) {
        __syncthreads();
        load_tileW(sW, Ws[widx], colBase, tid);
        __syncthreads();
        float acc[4][4] = {};
        mm_64x64(sA, sW, ty, tx, acc);
        float* O = Os[widx];
        bool relu = (widx == 0);
        #pragma unroll
        for (int i = 0; i < 4; i++) {
            float4 o4;
            o4.x = acc[i][0]; o4.y = acc[i][1]; o4.z = acc[i][2]; o4.w = acc[i][3];
            if (relu) {
                o4.x = fmaxf(o4.x, 0.f); o4.y = fmaxf(o4.y, 0.f);
                o4.z = fmaxf(o4.z, 0.f); o4.w = fmaxf(o4.w, 0.f);
            }
            *(float4*)&O[(rowBase + ty * 4 + i) * D + colBase + tx * 4] = o4;
        }
    }
}

template<bool RELU, bool RES>
__global__ __launch_bounds__(256) void gemm_kernel(const float* __restrict__ A,
        const float* __restrict__ W, const float* __restrict__ bias,
        const float* __restrict__ res, float* __restrict__ C) {
    extern __shared__ float smem[];
    float* sA = smem;
    float* sW = smem + 128 * GP;
    int tid = threadIdx.x;
    int rowBase = blockIdx.x * 64;
    int colBase = blockIdx.y * 64;
    int tx = tid & 15, ty = tid >> 4;

    load_tileA(sA, A, rowBase, tid);
    load_tileW(sW, W, colBase, tid);
    __syncthreads();
    float acc[4][4] = {};
    mm_64x64(sA, sW, ty, tx, acc);

    float4 b4 = *(const float4*)&bias[colBase + tx * 4];
    #pragma unroll
    for (int i = 0; i < 4; i++) {
        int row = rowBase + ty * 4 + i;
        float4 o4;
        o4.x = acc[i][0] + b4.x; o4.y = acc[i][1] + b4.y;
        o4.z = acc[i][2] + b4.z; o4.w = acc[i][3] + b4.w;
        if (RELU) {
            o4.x = fmaxf(o4.x, 0.f); o4.y = fmaxf(o4.y, 0.f);
            o4.z = fmaxf(o4.z, 0.f); o4.w = fmaxf(o4.w, 0.f);
        }
        if (RES) {
            float4 r4 = *(const float4*)&res[row * D + colBase + tx * 4];
            o4.x += r4.x; o4.y += r4.y; o4.z += r4.z; o4.w += r4.w;
        }
        *(float4*)&C[row * D + colBase + tx * 4] = o4;
    }
}

// ---------------- tf32 tensor-core flash attention ------------------------------
// grid (SEQ/64, B*H), 128 threads (4 warps, 16 queries each). Keys pre-compacted
// per batch. K/V tiles of 64 keys in smem; mma.sync.m16n8k8.tf32; online softmax
// in C-fragment registers; P via warp-private smem into A-fragments.
#define BQ 64
#define BK 64
#define KSTR 36   // K/V smem row stride (floats): conflict-free B-frag LDS for K
#define PSTR 68   // P smem row stride

__device__ __forceinline__ unsigned tf32r(float x) {
    unsigned u;
    asm("cvt.rna.tf32.f32 %0, %1;" : "=r"(u) : "f"(x));
    return u;
}

#define MMA_TF32(c, a, b0, b1) \
    asm volatile("mma.sync.aligned.m16n8k8.row.col.f32.tf32.tf32.f32 " \
        "{%0,%1,%2,%3}, {%4,%5,%6,%7}, {%8,%9}, {%0,%1,%2,%3};" \
        : "+f"(c[0]), "+f"(c[1]), "+f"(c[2]), "+f"(c[3]) \
        : "r"(a[0]), "r"(a[1]), "r"(a[2]), "r"(a[3]), "r"(b0), "r"(b1))

__global__ __launch_bounds__(128) void attn_mma_kernel(
        const float* __restrict__ gq, const float* __restrict__ gk,
        const float* __restrict__ gv, const int* __restrict__ idx,
        const int* __restrict__ cnt, float* __restrict__ out) {
    __shared__ float sK[BK][KSTR];
    __shared__ float sV[BK][KSTR];
    __shared__ float sP[4][16][PSTR];

    int tid  = threadIdx.x;
    int warp = tid >> 5, lane = tid & 31;
    int g = lane >> 2, tig = lane & 3;
    int b = blockIdx.y >> 2, h = blockIdx.y & 3;
    int q0 = blockIdx.x * BQ + warp * 16;
    int nb = cnt[b];
    const int* bidx = idx + b * SEQ;

    // Q fragments, pre-scaled, tf32-rounded
    const float scale = 0.17677669529663687f;  // 1/sqrt(32)
    const float* qp0 = gq + (size_t)(b * SEQ + q0 + g) * D + h * DK;
    const float* qp1 = qp0 + 8 * D;
    unsigned qa[4][4];
    #pragma unroll
    for (int ks = 0; ks < 4; ks++) {
        int k0 = ks * 8;
        qa[ks][0] = tf32r(qp0[k0 + tig]     * scale);
        qa[ks][1] = tf32r(qp1[k0 + tig]     * scale);
        qa[ks][2] = tf32r(qp0[k0 + tig + 4] * scale);
        qa[ks][3] = tf32r(qp1[k0 + tig + 4] * scale);
    }

    float m0r = -1e30f, m1r = -1e30f, l0 = 0.f, l1 = 0.f;
    float o[4][4] = {};

    for (int kb = 0; kb < nb; kb += BK) {
        int kv = min(BK, nb - kb);
        __syncthreads();
        // fill K/V tiles (tf32-rounded); pad with zeros
        for (int i = tid; i < BK * 8; i += 128) {
            int key = i >> 3, d4 = (i & 7) * 4;
            float4 kd = make_float4(0.f, 0.f, 0.f, 0.f), vd = kd;
            if (key < kv) {
                int gi = bidx[kb + key];
                const float* kp = gk + (size_t)(b * SEQ + gi) * D + h * DK + d4;
                const float* vp = gv + (size_t)(b * SEQ + gi) * D + h * DK + d4;
                kd = *(const float4*)kp;
                vd = *(const float4*)vp;
            }
            float4 kr, vr;
            kr.x = __uint_as_float(tf32r(kd.x)); kr.y = __uint_as_float(tf32r(kd.y));
            kr.z = __uint_as_float(tf32r(kd.z)); kr.w = __uint_as_float(tf32r(kd.w));
            vr.x = __uint_as_float(tf32r(vd.x)); vr.y = __uint_as_float(tf32r(vd.y));
            vr.z = __uint_as_float(tf32r(vd.z)); vr.w = __uint_as_float(tf32r(vd.w));
            *(float4*)&sK[key][d4] = kr;
            *(float4*)&sV[key][d4] = vr;
        }
        __syncthreads();

        // S = Q K^T : 8 n-tiles (8 keys each) x 4 k-steps
        float s[8][4];
        #pragma unroll
        for (int nt = 0; nt < 8; nt++) { s[nt][0]=0.f; s[nt][1]=0.f; s[nt][2]=0.f; s[nt][3]=0.f; }
        #pragma unroll
        for (int nt = 0; nt < 8; nt++) {
            #pragma unroll
            for (int ks = 0; ks < 4; ks++) {
                unsigned b0 = __float_as_uint(sK[nt*8 + g][ks*8 + tig]);
                unsigned b1 = __float_as_uint(sK[nt*8 + g][ks*8 + tig + 4]);
                MMA_TF32(s[nt], qa[ks], b0, b1);
            }
        }

        // invalidate padded columns
        #pragma unroll
        for (int nt = 0; nt < 8; nt++) {
            int col = nt * 8 + 2 * tig;
            if (col     >= kv) { s[nt][0] = -1e30f; s[nt][2] = -1e30f; }
            if (col + 1 >= kv) { s[nt][1] = -1e30f; s[nt][3] = -1e30f; }
        }

        // row max (rows g and g+8)
        float bm0 = -1e30f, bm1 = -1e30f;
        #pragma unroll
        for (int nt = 0; nt < 8; nt++) {
            bm0 = fmaxf(bm0, fmaxf(s[nt][0], s[nt][1]));
            bm1 = fmaxf(bm1, fmaxf(s[nt][2], s[nt][3]));
        }
        bm0 = fmaxf(bm0, __shfl_xor_sync(0xffffffffu, bm0, 1));
        bm0 = fmaxf(bm0, __shfl_xor_sync(0xffffffffu, bm0, 2));
        bm1 = fmaxf(bm1, __shfl_xor_sync(0xffffffffu, bm1, 1));
        bm1 = fmaxf(bm1, __shfl_xor_sync(0xffffffffu, bm1, 2));

        float mn0 = fmaxf(m0r, bm0), mn1 = fmaxf(m1r, bm1);
        float cr0 = __expf(m0r - mn0), cr1 = __expf(m1r - mn1);
        m0r = mn0; m1r = mn1;
        #pragma unroll
        for (int nt = 0; nt < 4; nt++) {
            o[nt][0] *= cr0; o[nt][1] *= cr0;
            o[nt][2] *= cr1; o[nt][3] *= cr1;
        }

        // P = exp(S - m), row sums, store tf32 P to warp-private smem
        __syncwarp();
        float rs0 = 0.f, rs1 = 0.f;
        #pragma unroll
        for (int nt = 0; nt < 8; nt++) {
            float p0 = __expf(s[nt][0] - mn0);
            float p1 = __expf(s[nt][1] - mn0);
            float p2 = __expf(s[nt][2] - mn1);
            float p3 = __expf(s[nt][3] - mn1);
            rs0 += p0 + p1; rs1 += p2 + p3;
            int col = nt * 8 + 2 * tig;
            *(float2*)&sP[warp][g][col] =
                make_float2(__uint_as_float(tf32r(p0)), __uint_as_float(tf32r(p1)));
            *(float2*)&sP[warp][g + 8][col] =
                make_float2(__uint_as_float(tf32r(p2)), __uint_as_float(tf32r(p3)));
        }
        rs0 += __shfl_xor_sync(0xffffffffu, rs0, 1);
        rs0 += __shfl_xor_sync(0xffffffffu, rs0, 2);
        rs1 += __shfl_xor_sync(0xffffffffu, rs1, 1);
        rs1 += __shfl_xor_sync(0xffffffffu, rs1, 2);
        l0 = l0 * cr0 + rs0;
        l1 = l1 * cr1 + rs1;
        __syncwarp();

        // O += P V : 4 n-tiles (d) x 8 k-steps (keys)
        #pragma unroll
        for (int ks = 0; ks < 8; ks++) {
            unsigned a[4];
            a[0] = __float_as_uint(sP[warp][g    ][ks*8 + tig]);
            a[1] = __float_as_uint(sP[warp][g + 8][ks*8 + tig]);
            a[2] = __float_as_uint(sP[warp][g    ][ks*8 + tig + 4]);
            a[3] = __float_as_uint(sP[warp][g + 8][ks*8 + tig + 4]);
            #pragma unroll
            for (int nt = 0; nt < 4; nt++) {
                unsigned b0 = __float_as_uint(sV[ks*8 + tig    ][nt*8 + g]);
                unsigned b1 = __float_as_uint(sV[ks*8 + tig + 4][nt*8 + g]);
                MMA_TF32(o[nt], a, b0, b1);
            }
        }
    }

    float inv0 = (l0 > 0.f) ? 1.f / l0 : 0.f;
    float inv1 = (l1 > 0.f) ? 1.f / l1 : 0.f;
    float* op0 = out + (size_t)(b * SEQ + q0 + g) * D + h * DK;
    float* op1 = op0 + 8 * D;
    #pragma unroll
    for (int nt = 0; nt < 4; nt++) {
        int col = nt * 8 + 2 * tig;
        *(float2*)(op0 + col) = make_float2(o[nt][0] * inv0, o[nt][1] * inv0);
        *(float2*)(op1 + col) = make_float2(o[nt][2] * inv1, o[nt][3] * inv1);
    }
}

// ---------------- launch ---------------------------------------------------------
extern "C" void kernel_launch(void* const* d_in, const int* in_sizes, int n_in,
                              void* d_out, int out_size) {
    const float* x    = (const float*)d_in[0];
    const int*   mask = (const int*)  d_in[1];
    const float* ln_w = (const float*)d_in[2];
    const float* ln_b = (const float*)d_in[3];
    const float* wq   = (const float*)d_in[4];
    const float* wk   = (const float*)d_in[5];
    const float* wv   = (const float*)d_in[6];
    const float* w1   = (const float*)d_in[7];
    const float* b1   = (const float*)d_in[8];
    const float* w2   = (const float*)d_in[9];
    const float* b2   = (const float*)d_in[10];
    float* out = (float*)d_out;

    float *xn, *q, *k, *v, *attn, *sa, *h, *f1;
    int *cntp, *idxp;
    cudaGetSymbolAddress((void**)&xn,   g_xn);
    cudaGetSymbolAddress((void**)&q,    g_q);
    cudaGetSymbolAddress((void**)&k,    g_k);
    cudaGetSymbolAddress((void**)&v,    g_v);
    cudaGetSymbolAddress((void**)&attn, g_attn);
    cudaGetSymbolAddress((void**)&sa,   g_sa);
    cudaGetSymbolAddress((void**)&h,    g_h);
    cudaGetSymbolAddress((void**)&f1,   g_f1);
    cudaGetSymbolAddress((void**)&cntp, g_cnt);
    cudaGetSymbolAddress((void**)&idxp, g_idx);

    cudaFuncSetAttribute(qkv_kernel, cudaFuncAttributeMaxDynamicSharedMemorySize, GEMM_SMEM);
    cudaFuncSetAttribute(gemm_kernel<true,false>,  cudaFuncAttributeMaxDynamicSharedMemorySize, GEMM_SMEM);
    cudaFuncSetAttribute(gemm_kernel<false,true>,  cudaFuncAttributeMaxDynamicSharedMemorySize, GEMM_SMEM);

    // 0) compact unmasked key indices per batch (deterministic scan)
    compact_kernel<<<BATCH, 1024>>>(mask, idxp, cntp);
    // 1) xn = LN(x)
    ln_kernel<<<ROWS/8, 256>>>(x, nullptr, nullptr, xn, ln_w, ln_b);
    // 2) q=relu(xn@wq^T), k, v
    qkv_kernel<<<dim3(ROWS/64, 2), 256, GEMM_SMEM>>>(xn, wq, wk, wv, q, k, v);
    // 3) attention (tf32 tensor cores over compacted keys)
    attn_mma_kernel<<<dim3(SEQ/BQ, BATCH*H), 128>>>(q, k, v, idxp, cntp, attn);
    // 4) sa = xn + attn ; h = LN(sa)
    ln_kernel<<<ROWS/8, 256>>>(attn, xn, sa, h, ln_w, ln_b);
    // 5) f1 = relu(h@w1^T + b1)
    gemm_kernel<true,false><<<dim3(ROWS/64, 2), 256, GEMM_SMEM>>>(h, w1, b1, nullptr, f1);
    // 6) out = sa + f1@w2^T + b2
    gemm_kernel<false,true><<<dim3(ROWS/64, 2), 256, GEMM_SMEM>>>(f1, w2, b2, sa, out);
}

// round 3
// speedup vs baseline: 5.0556x; 2.4440x over previous
#include <cuda_runtime.h>
#include <cuda_bf16.h>
#include <math.h>

#define D 128
#define H 4
#define DK 32
#define BATCH 16
#define SEQ 2048
#define ROWS (BATCH*SEQ)   // 32768
#define LNEPS 1e-5f

// ---------------- scratch (static device globals; no allocs allowed) ----------
__device__ float g_xn[ROWS*D];
__device__ float g_q [ROWS*D];
__device__ float g_k [ROWS*D];
__device__ float g_v [ROWS*D];
__device__ float g_attn[ROWS*D];
__device__ float g_sa[ROWS*D];
__device__ float g_h [ROWS*D];
__device__ float g_f1[ROWS*D];
__device__ float g_zb[D];                 // zero bias (zero-initialized)
__device__ int   g_cnt[BATCH];
__device__ int   g_idx[BATCH*SEQ];
__device__ __nv_bfloat16 g_kc[ROWS*D];    // compacted bf16 K
__device__ __nv_bfloat16 g_vc[ROWS*D];    // compacted bf16 V

// ---------------- helpers ------------------------------------------------------
__device__ __forceinline__ unsigned tf32r(float x) {
    unsigned u;
    asm("cvt.rna.tf32.f32 %0, %1;" : "=r"(u) : "f"(x));
    return u;
}
__device__ __forceinline__ unsigned packbf(float a, float b) {
    __nv_bfloat162 t = __floats2bfloat162_rn(a, b);
    return *(unsigned*)&t;
}

#define MMA_TF32(c, a, b0, b1) \
    asm volatile("mma.sync.aligned.m16n8k8.row.col.f32.tf32.tf32.f32 " \
        "{%0,%1,%2,%3}, {%4,%5,%6,%7}, {%8,%9}, {%0,%1,%2,%3};" \
        : "+f"(c[0]), "+f"(c[1]), "+f"(c[2]), "+f"(c[3]) \
        : "r"(a[0]), "r"(a[1]), "r"(a[2]), "r"(a[3]), "r"(b0), "r"(b1))

#define MMA_BF16(c, a, b0, b1) \
    asm volatile("mma.sync.aligned.m16n8k16.row.col.f32.bf16.bf16.f32 " \
        "{%0,%1,%2,%3}, {%4,%5,%6,%7}, {%8,%9}, {%0,%1,%2,%3};" \
        : "+f"(c[0]), "+f"(c[1]), "+f"(c[2]), "+f"(c[3]) \
        : "r"(a[0]), "r"(a[1]), "r"(a[2]), "r"(a[3]), "r"(b0), "r"(b1))

#define LDSM_X4(r, addr) \
    asm volatile("ldmatrix.sync.aligned.m8n8.x4.shared.b16 {%0,%1,%2,%3}, [%4];" \
        : "=r"(r[0]), "=r"(r[1]), "=r"(r[2]), "=r"(r[3]) : "r"(addr))

#define LDSM_X4_T(r, addr) \
    asm volatile("ldmatrix.sync.aligned.m8n8.x4.trans.shared.b16 {%0,%1,%2,%3}, [%4];" \
        : "=r"(r[0]), "=r"(r[1]), "=r"(r[2]), "=r"(r[3]) : "r"(addr))

// ---------------- LayerNorm (optionally fused residual add) -------------------
__global__ void ln_kernel(const float* __restrict__ in, const float* __restrict__ add,
                          float* __restrict__ sum_out, float* __restrict__ ln_out,
                          const float* __restrict__ w, const float* __restrict__ b) {
    int row  = blockIdx.x * 8 + (threadIdx.x >> 5);
    int lane = threadIdx.x & 31;
    const float4* ip = (const float4*)(in + row * D);
    float4 v = ip[lane];
    if (add != nullptr) {
        float4 a = ((const float4*)(add + row * D))[lane];
        v.x += a.x; v.y += a.y; v.z += a.z; v.w += a.w;
        ((float4*)(sum_out + row * D))[lane] = v;
    }
    float s = v.x + v.y + v.z + v.w;
    #pragma unroll
    for (int o = 16; o; o >>= 1) s += __shfl_xor_sync(0xffffffffu, s, o);
    float mu = s * (1.0f / D);
    float dx = v.x - mu, dy = v.y - mu, dz = v.z - mu, dw = v.w - mu;
    float ss = dx*dx + dy*dy + dz*dz + dw*dw;
    #pragma unroll
    for (int o = 16; o; o >>= 1) ss += __shfl_xor_sync(0xffffffffu, ss, o);
    float rstd = rsqrtf(ss * (1.0f / D) + LNEPS);
    float4 wv = ((const float4*)w)[lane];
    float4 bv = ((const float4*)b)[lane];
    float4 o4;
    o4.x = dx * rstd * wv.x + bv.x;
    o4.y = dy * rstd * wv.y + bv.y;
    o4.z = dz * rstd * wv.z + bv.z;
    o4.w = dw * rstd * wv.w + bv.w;
    ((float4*)(ln_out + row * D))[lane] = o4;
}

// ---------------- mask compaction (deterministic, order-preserving) -----------
__global__ void compact_kernel(const int* __restrict__ mask,
                               int* __restrict__ idx, int* __restrict__ cnt) {
    int b = blockIdx.x, t = threadIdx.x;
    const int* mb = mask + b * SEQ;
    int m0 = mb[2*t], m1 = mb[2*t+1];
    int s = m0 + m1;
    int lane = t & 31, w = t >> 5;
    int v = s;
    #pragma unroll
    for (int o = 1; o < 32; o <<= 1) {
        int u = __shfl_up_sync(0xffffffffu, v, o);
        if (lane >= o) v += u;
    }
    __shared__ int wsum[32];
    if (lane == 31) wsum[w] = v;
    __syncthreads();
    if (t < 32) {
        int u = wsum[t];
        #pragma unroll
        for (int o = 1; o < 32; o <<= 1) {
            int x = __shfl_up_sync(0xffffffffu, u, o);
            if (t >= o) u += x;
        }
        wsum[t] = u;
    }
    __syncthreads();
    int p = v - s + (w ? wsum[w-1] : 0);
    if (m0) idx[b*SEQ + p++] = 2*t;
    if (m1) idx[b*SEQ + p]   = 2*t + 1;
    if (t == 1023) cnt[b] = wsum[31];
}

// ---------------- gather + convert K/V to compacted bf16 ----------------------
__global__ void kvc_kernel(const float* __restrict__ k, const float* __restrict__ v,
                           const int* __restrict__ idx, const int* __restrict__ cnt,
                           __nv_bfloat16* __restrict__ kc, __nv_bfloat16* __restrict__ vc) {
    int b = blockIdx.y;
    int p = blockIdx.x * 8 + (threadIdx.x >> 5);
    int lane = threadIdx.x & 31;
    if (p >= cnt[b]) return;
    int gi = idx[b * SEQ + p];
    size_t src = (size_t)(b * SEQ + gi) * D + lane * 4;
    size_t dst = (size_t)(b * SEQ + p)  * D + lane * 4;
    float4 kv4 = *(const float4*)&k[src];
    float4 vv4 = *(const float4*)&v[src];
    __nv_bfloat162 r[2];
    r[0] = __floats2bfloat162_rn(kv4.x, kv4.y);
    r[1] = __floats2bfloat162_rn(kv4.z, kv4.w);
    *(uint2*)&kc[dst] = *(uint2*)r;
    r[0] = __floats2bfloat162_rn(vv4.x, vv4.y);
    r[1] = __floats2bfloat162_rn(vv4.z, vv4.w);
    *(uint2*)&vc[dst] = *(uint2*)r;
}

// ---------------- tf32 tensor-core GEMM: C[M,128] = A[M,128] @ W[128,128]^T ----
// block: 256 thr (8 warps), tile 128 rows x 128 cols, K chunked by 64.
// smem stride 68 (= 4 mod 32) -> conflict-free fragment LDS.
#define GSTR 68
#define GEMM_SMEM (2*128*GSTR*4)

template<bool RELU, bool RES>
__global__ __launch_bounds__(256) void gemm_tf32(const float* __restrict__ A,
        const float* __restrict__ W, const float* __restrict__ bias,
        const float* __restrict__ res, float* __restrict__ C) {
    extern __shared__ float sm[];
    float* sA = sm;
    float* sW = sm + 128 * GSTR;
    int tid = threadIdx.x;
    int warp = tid >> 5, lane = tid & 31;
    int g = lane >> 2, tig = lane & 3;
    int rowBase = blockIdx.x * 128;

    float c[16][4] = {};

    #pragma unroll
    for (int kc = 0; kc < 2; kc++) {
        __syncthreads();
        for (int i = tid; i < 2048; i += 256) {
            int r = i >> 4, c4 = (i & 15) * 4;
            float4 a4 = *(const float4*)&A[(size_t)(rowBase + r) * D + kc * 64 + c4];
            float4 w4 = *(const float4*)&W[(size_t)r * D + kc * 64 + c4];
            float4 at, wt;
            at.x = __uint_as_float(tf32r(a4.x)); at.y = __uint_as_float(tf32r(a4.y));
            at.z = __uint_as_float(tf32r(a4.z)); at.w = __uint_as_float(tf32r(a4.w));
            wt.x = __uint_as_float(tf32r(w4.x)); wt.y = __uint_as_float(tf32r(w4.y));
            wt.z = __uint_as_float(tf32r(w4.z)); wt.w = __uint_as_float(tf32r(w4.w));
            *(float4*)&sA[r * GSTR + c4] = at;
            *(float4*)&sW[r * GSTR + c4] = wt;
        }
        __syncthreads();

        #pragma unroll
        for (int k8 = 0; k8 < 8; k8++) {
            int kb = k8 * 8;
            int r0 = warp * 16 + g;
            unsigned a[4];
            a[0] = __float_as_uint(sA[r0 * GSTR + kb + tig]);
            a[1] = __float_as_uint(sA[(r0 + 8) * GSTR + kb + tig]);
            a[2] = __float_as_uint(sA[r0 * GSTR + kb + tig + 4]);
            a[3] = __float_as_uint(sA[(r0 + 8) * GSTR + kb + tig + 4]);
            #pragma unroll
            for (int nt = 0; nt < 16; nt++) {
                unsigned b0 = __float_as_uint(sW[(nt * 8 + g) * GSTR + kb + tig]);
                unsigned b1 = __float_as_uint(sW[(nt * 8 + g) * GSTR + kb + tig + 4]);
                MMA_TF32(c[nt], a, b0, b1);
            }
        }
    }

    // epilogue
    int row0 = rowBase + warp * 16 + g;
    #pragma unroll
    for (int nt = 0; nt < 16; nt++) {
        int col = nt * 8 + 2 * tig;
        float2 bb = *(const float2*)&bias[col];
        float2 lo = make_float2(c[nt][0] + bb.x, c[nt][1] + bb.y);
        float2 hi = make_float2(c[nt][2] + bb.x, c[nt][3] + bb.y);
        if (RELU) {
            lo.x = fmaxf(lo.x, 0.f); lo.y = fmaxf(lo.y, 0.f);
            hi.x = fmaxf(hi.x, 0.f); hi.y = fmaxf(hi.y, 0.f);
        }
        if (RES) {
            float2 r0v = *(const float2*)&res[(size_t)row0 * D + col];
            float2 r1v = *(const float2*)&res[(size_t)(row0 + 8) * D + col];
            lo.x += r0v.x; lo.y += r0v.y; hi.x += r1v.x; hi.y += r1v.y;
        }
        *(float2*)&C[(size_t)row0 * D + col] = lo;
        *(float2*)&C[(size_t)(row0 + 8) * D + col] = hi;
    }
}

// ---------------- bf16 flash attention (ldmatrix + m16n8k16) -------------------
// grid (SEQ/128, B*H), 256 thr (8 warps, 16 q each). BK=64 keys/step over
// compacted bf16 K/V. Row stride 40 bf16 (80B) -> conflict-free ldmatrix.
#define AKS 40
__global__ __launch_bounds__(256) void attn_bf16_kernel(
        const float* __restrict__ gq, const __nv_bfloat16* __restrict__ gkc,
        const __nv_bfloat16* __restrict__ gvc, const int* __restrict__ cnt,
        float* __restrict__ out) {
    __shared__ __nv_bfloat16 sK[64][AKS];
    __shared__ __nv_bfloat16 sV[64][AKS];

    int tid = threadIdx.x;
    int warp = tid >> 5, lane = tid & 31;
    int g = lane >> 2, tig = lane & 3;
    int b = blockIdx.y >> 2, h = blockIdx.y & 3;
    int q0 = blockIdx.x * 128 + warp * 16;
    int nb = cnt[b];

    // Q fragments, scaled by 1/sqrt(dk)*log2(e), bf16-packed
    const float qs = 0.17677669529663687f * 1.4426950408889634f;
    const float* qp0 = gq + (size_t)(b * SEQ + q0 + g) * D + h * DK;
    const float* qp1 = qp0 + 8 * D;
    unsigned qa[2][4];
    #pragma unroll
    for (int ks = 0; ks < 2; ks++) {
        int base = ks * 16 + 2 * tig;
        qa[ks][0] = packbf(qp0[base] * qs,     qp0[base + 1] * qs);
        qa[ks][1] = packbf(qp1[base] * qs,     qp1[base + 1] * qs);
        qa[ks][2] = packbf(qp0[base + 8] * qs, qp0[base + 9] * qs);
        qa[ks][3] = packbf(qp1[base + 8] * qs, qp1[base + 9] * qs);
    }

    float m0r = -1e30f, m1r = -1e30f, l0 = 0.f, l1 = 0.f;
    float o[4][4] = {};

    // ldmatrix source addresses (lane-dependent, loop-invariant offsets)
    unsigned kAddr = (unsigned)__cvta_generic_to_shared(
        &sK[(lane & 7)][ (lane >> 3) * 8 ]);
    int vKey = ((lane >> 3) & 1) * 8 + (lane & 7);
    int vCol = (lane >> 4) * 8;

    for (int kb = 0; kb < nb; kb += 64) {
        int kv = min(64, nb - kb);
        __syncthreads();
        {   // fill: 256 threads x 16B per tensor
            int key = tid >> 2, seg = (tid & 3) * 8;
            const uint4* ksrc = (const uint4*)(gkc + (size_t)(b * SEQ + kb + key) * D + h * DK + seg);
            const uint4* vsrc = (const uint4*)(gvc + (size_t)(b * SEQ + kb + key) * D + h * DK + seg);
            uint4 kd = make_uint4(0,0,0,0), vd = kd;
            if (key < kv) { kd = *ksrc; vd = *vsrc; }
            *(uint4*)&sK[key][seg] = kd;
            *(uint4*)&sV[key][seg] = vd;
        }
        __syncthreads();

        // S = Q K^T
        float s[8][4];
        #pragma unroll
        for (int nt = 0; nt < 8; nt++) {
            s[nt][0] = 0.f; s[nt][1] = 0.f; s[nt][2] = 0.f; s[nt][3] = 0.f;
            unsigned kf[4];
            LDSM_X4(kf, kAddr + nt * 8 * AKS * 2);
            MMA_BF16(s[nt], qa[0], kf[0], kf[1]);
            MMA_BF16(s[nt], qa[1], kf[2], kf[3]);
        }

        if (kv < 64) {
            #pragma unroll
            for (int nt = 0; nt < 8; nt++) {
                int col = nt * 8 + 2 * tig;
                if (col     >= kv) { s[nt][0] = -1e30f; s[nt][2] = -1e30f; }
                if (col + 1 >= kv) { s[nt][1] = -1e30f; s[nt][3] = -1e30f; }
            }
        }

        // online softmax (log2 domain)
        float bm0 = -1e30f, bm1 = -1e30f;
        #pragma unroll
        for (int nt = 0; nt < 8; nt++) {
            bm0 = fmaxf(bm0, fmaxf(s[nt][0], s[nt][1]));
            bm1 = fmaxf(bm1, fmaxf(s[nt][2], s[nt][3]));
        }
        bm0 = fmaxf(bm0, __shfl_xor_sync(0xffffffffu, bm0, 1));
        bm0 = fmaxf(bm0, __shfl_xor_sync(0xffffffffu, bm0, 2));
        bm1 = fmaxf(bm1, __shfl_xor_sync(0xffffffffu, bm1, 1));
        bm1 = fmaxf(bm1, __shfl_xor_sync(0xffffffffu, bm1, 2));
        float mn0 = fmaxf(m0r, bm0), mn1 = fmaxf(m1r, bm1);
        float cr0 = exp2f(m0r - mn0), cr1 = exp2f(m1r - mn1);
        m0r = mn0; m1r = mn1;
        #pragma unroll
        for (int nt = 0; nt < 4; nt++) {
            o[nt][0] *= cr0; o[nt][1] *= cr0;
            o[nt][2] *= cr1; o[nt][3] *= cr1;
        }

        // P = exp2(S - m), packed straight into PV A-fragments
        unsigned p01[8], p23[8];
        float rs0 = 0.f, rs1 = 0.f;
        #pragma unroll
        for (int nt = 0; nt < 8; nt++) {
            float p0 = exp2f(s[nt][0] - mn0);
            float p1 = exp2f(s[nt][1] - mn0);
            float p2 = exp2f(s[nt][2] - mn1);
            float p3 = exp2f(s[nt][3] - mn1);
            rs0 += p0 + p1; rs1 += p2 + p3;
            p01[nt] = packbf(p0, p1);
            p23[nt] = packbf(p2, p3);
        }
        rs0 += __shfl_xor_sync(0xffffffffu, rs0, 1);
        rs0 += __shfl_xor_sync(0xffffffffu, rs0, 2);
        rs1 += __shfl_xor_sync(0xffffffffu, rs1, 1);
        rs1 += __shfl_xor_sync(0xffffffffu, rs1, 2);
        l0 = l0 * cr0 + rs0;
        l1 = l1 * cr1 + rs1;

        // O += P V  (V via ldmatrix.trans)
        #pragma unroll
        for (int ksp = 0; ksp < 4; ksp++) {
            unsigned pa[4] = { p01[2*ksp], p23[2*ksp], p01[2*ksp+1], p23[2*ksp+1] };
            #pragma unroll
            for (int dh = 0; dh < 2; dh++) {
                unsigned vb[4];
                unsigned vAddr = (unsigned)__cvta_generic_to_shared(
                    &sV[ksp * 16 + vKey][dh * 16 + vCol]);
                LDSM_X4_T(vb, vAddr);
                MMA_BF16(o[dh*2 + 0], pa, vb[0], vb[1]);
                MMA_BF16(o[dh*2 + 1], pa, vb[2], vb[3]);
            }
        }
    }

    float inv0 = (l0 > 0.f) ? 1.f / l0 : 0.f;
    float inv1 = (l1 > 0.f) ? 1.f / l1 : 0.f;
    float* op0 = out + (size_t)(b * SEQ + q0 + g) * D + h * DK;
    float* op1 = op0 + 8 * D;
    #pragma unroll
    for (int nt = 0; nt < 4; nt++) {
        int col = nt * 8 + 2 * tig;
        *(float2*)(op0 + col) = make_float2(o[nt][0] * inv0, o[nt][1] * inv0);
        *(float2*)(op1 + col) = make_float2(o[nt][2] * inv1, o[nt][3] * inv1);
    }
}

// ---------------- launch ---------------------------------------------------------
extern "C" void kernel_launch(void* const* d_in, const int* in_sizes, int n_in,
                              void* d_out, int out_size) {
    const float* x    = (const float*)d_in[0];
    const int*   mask = (const int*)  d_in[1];
    const float* ln_w = (const float*)d_in[2];
    const float* ln_b = (const float*)d_in[3];
    const float* wq   = (const float*)d_in[4];
    const float* wk   = (const float*)d_in[5];
    const float* wv   = (const float*)d_in[6];
    const float* w1   = (const float*)d_in[7];
    const float* b1   = (const float*)d_in[8];
    const float* w2   = (const float*)d_in[9];
    const float* b2   = (const float*)d_in[10];
    float* out = (float*)d_out;

    float *xn, *q, *k, *v, *attn, *sa, *h, *f1, *zb;
    int *cntp, *idxp;
    __nv_bfloat16 *kc, *vc;
    cudaGetSymbolAddress((void**)&xn,   g_xn);
    cudaGetSymbolAddress((void**)&q,    g_q);
    cudaGetSymbolAddress((void**)&k,    g_k);
    cudaGetSymbolAddress((void**)&v,    g_v);
    cudaGetSymbolAddress((void**)&attn, g_attn);
    cudaGetSymbolAddress((void**)&sa,   g_sa);
    cudaGetSymbolAddress((void**)&h,    g_h);
    cudaGetSymbolAddress((void**)&f1,   g_f1);
    cudaGetSymbolAddress((void**)&zb,   g_zb);
    cudaGetSymbolAddress((void**)&cntp, g_cnt);
    cudaGetSymbolAddress((void**)&idxp, g_idx);
    cudaGetSymbolAddress((void**)&kc,   g_kc);
    cudaGetSymbolAddress((void**)&vc,   g_vc);

    cudaFuncSetAttribute(gemm_tf32<true,false>,  cudaFuncAttributeMaxDynamicSharedMemorySize, GEMM_SMEM);
    cudaFuncSetAttribute(gemm_tf32<false,false>, cudaFuncAttributeMaxDynamicSharedMemorySize, GEMM_SMEM);
    cudaFuncSetAttribute(gemm_tf32<false,true>,  cudaFuncAttributeMaxDynamicSharedMemorySize, GEMM_SMEM);

    // 0) compact unmasked key indices per batch
    compact_kernel<<<BATCH, 1024>>>(mask, idxp, cntp);
    // 1) xn = LN(x)
    ln_kernel<<<ROWS/8, 256>>>(x, nullptr, nullptr, xn, ln_w, ln_b);
    // 2) q=relu(xn@wq^T), k=xn@wk^T, v=xn@wv^T  (tf32 MMA)
    gemm_tf32<true,false> <<<ROWS/128, 256, GEMM_SMEM>>>(xn, wq, zb, nullptr, q);
    gemm_tf32<false,false><<<ROWS/128, 256, GEMM_SMEM>>>(xn, wk, zb, nullptr, k);
    gemm_tf32<false,false><<<ROWS/128, 256, GEMM_SMEM>>>(xn, wv, zb, nullptr, v);
    // 3) gather+convert compacted bf16 K/V
    kvc_kernel<<<dim3(SEQ/8, BATCH), 256>>>(k, v, idxp, cntp, kc, vc);
    // 4) attention (bf16 tensor cores over compacted keys)
    attn_bf16_kernel<<<dim3(SEQ/128, BATCH*H), 256>>>(q, kc, vc, cntp, attn);
    // 5) sa = xn + attn ; h = LN(sa)
    ln_kernel<<<ROWS/8, 256>>>(attn, xn, sa, h, ln_w, ln_b);
    // 6) f1 = relu(h@w1^T + b1)
    gemm_tf32<true,false><<<ROWS/128, 256, GEMM_SMEM>>>(h, w1, b1, nullptr, f1);
    // 7) out = sa + f1@w2^T + b2
    gemm_tf32<false,true><<<ROWS/128, 256, GEMM_SMEM>>>(f1, w2, b2, sa, out);
}